// round 11
// baseline (speedup 1.0000x reference)
#include <cuda_runtime.h>
#include <math.h>

#define NH 4
#define NN 1024
#define EE 4096
#define NLE 16384
#define FN 128
#define FE 64
#define NODE_OUT_SZ (NH*NN*FN)   /* 524288 */
#define NBLK 296
#define NTHR 256

// ---------------- scratch (device globals; zero-initialized at load) ----------------
__device__ float g_nv[NN*NH*FN];
__device__ float g_ev[EE*NH*FE];
__device__ float g_nk[NN*NH];          // flat k-linear output [row][c]
__device__ float g_ek[EE*NH];
__device__ float g_yn[NH*512];         // y[h][b*128+f]  (atomics; zeroed each run)
__device__ float g_ye[NH*256];
__device__ float g_ksn[16];            // ks[h][b]       (atomics; zeroed each run)
__device__ float g_kse[16];
__device__ float g_tn[NH*FN];          // t[h][f]
__device__ float g_te[NH*FE];
__device__ float g_un[NH*512];         // u[h][b*128+j]
__device__ float g_ue[NH*256];
__device__ float g_cn[16];             // c[h][b]
__device__ float g_ce[16];
__device__ float g_nsa[NH*NN];         // raw scores
__device__ float g_esa[NH*EE];
__device__ float g_nsa2[NH*NN];        // softmaxed (separate buffer)
__device__ float g_esa2[NH*EE];
__device__ int   g_cnt_n[NN], g_fc_n[NN], g_off_n[NN+1], g_lst_n[EE];
__device__ int   g_cnt_e[EE], g_fc_e[EE], g_off_e[EE+1], g_lst_e[NLE];
__device__ float g_ncWT[FN*FN];
__device__ float g_ecWT[FE*FE];
__device__ float g_nqWT[FN*512];       // nqWT[j*512+o] = nqW[o*128+j]
__device__ float g_eqWT[FE*256];       // eqWT[j*256+o] = eqW[o*64+j]
__device__ unsigned int g_barcnt;      // grid barrier state
__device__ unsigned int g_bargen;

// ---------------- helpers ----------------
__device__ __forceinline__ float wredsum(float v)
{
#pragma unroll
    for (int o = 16; o; o >>= 1) v += __shfl_xor_sync(0xffffffffu, v, o);
    return v;
}

// Cheap grid barrier: one atomic per block for arrival; releases observed via
// plain volatile LOADS (no L2 atomic-ALU serialization) with nanosleep backoff.
__device__ __forceinline__ void grid_sync()
{
    __syncthreads();
    if (threadIdx.x == 0) {
        volatile unsigned int* vgen = &g_bargen;
        unsigned int gen = *vgen;
        __threadfence();
        unsigned int arrived = atomicAdd(&g_barcnt, 1u);
        if (arrived == NBLK - 1) {
            g_barcnt = 0;
            __threadfence();
            *vgen = gen + 1;
        } else {
            while (*vgen == gen) { __nanosleep(64); }
        }
    }
    __syncthreads();
}

__device__ __forceinline__ float blkmax(float v, float* s)
{
    int lane = threadIdx.x & 31, warp = threadIdx.x >> 5;
#pragma unroll
    for (int o = 16; o; o >>= 1) v = fmaxf(v, __shfl_xor_sync(0xffffffffu, v, o));
    if (lane == 0) s[warp] = v;
    __syncthreads();
    if (warp == 0) {
        float x = (lane < 8) ? s[lane] : -3e38f;
#pragma unroll
        for (int o = 4; o; o >>= 1) x = fmaxf(x, __shfl_xor_sync(0xffffffffu, x, o));
        if (lane == 0) s[0] = x;
    }
    __syncthreads();
    float r = s[0];
    __syncthreads();
    return r;
}

__device__ __forceinline__ float blksum(float v, float* s)
{
    int lane = threadIdx.x & 31, warp = threadIdx.x >> 5;
    v = wredsum(v);
    if (lane == 0) s[warp] = v;
    __syncthreads();
    if (warp == 0) {
        float x = (lane < 8) ? s[lane] : 0.f;
#pragma unroll
        for (int o = 4; o; o >>= 1) x += __shfl_xor_sync(0xffffffffu, x, o);
        if (lane == 0) s[0] = x;
    }
    __syncthreads();
    float r = s[0];
    __syncthreads();
    return r;
}

// gemm tile: C[64,64] block of A[M,K] @ W[N,K]^T + bias, using caller shared buffer
__device__ __forceinline__
void gemm_tile(const float* __restrict__ A, const float* __restrict__ W,
               const float* __restrict__ bias, float* __restrict__ C,
               int bm, int bn, int Nout, int K, float* sbuf)
{
    float (*As)[64] = reinterpret_cast<float(*)[64]>(sbuf);
    float (*Bs)[64] = reinterpret_cast<float(*)[64]>(sbuf + 32*64);
    int tid = threadIdx.x;
    int tx = tid & 15, ty = tid >> 4;

    float acc[4][4];
#pragma unroll
    for (int i = 0; i < 4; i++)
#pragma unroll
        for (int j = 0; j < 4; j++) acc[i][j] = 0.f;

    for (int k0 = 0; k0 < K; k0 += 32) {
#pragma unroll
        for (int j = 0; j < 2; j++) {
            int f4 = tid + j * 256;
            int m  = f4 >> 3;
            int k4 = f4 & 7;
            float4 va = *reinterpret_cast<const float4*>(&A[(size_t)(bm + m) * K + k0 + k4 * 4]);
            As[k4*4+0][m] = va.x; As[k4*4+1][m] = va.y; As[k4*4+2][m] = va.z; As[k4*4+3][m] = va.w;
            float4 vb = *reinterpret_cast<const float4*>(&W[(size_t)(bn + m) * K + k0 + k4 * 4]);
            Bs[k4*4+0][m] = vb.x; Bs[k4*4+1][m] = vb.y; Bs[k4*4+2][m] = vb.z; Bs[k4*4+3][m] = vb.w;
        }
        __syncthreads();
#pragma unroll
        for (int kk = 0; kk < 32; kk++) {
            float4 a = *reinterpret_cast<const float4*>(&As[kk][ty * 4]);
            float4 b = *reinterpret_cast<const float4*>(&Bs[kk][tx * 4]);
            float ra[4] = {a.x, a.y, a.z, a.w};
            float rb[4] = {b.x, b.y, b.z, b.w};
#pragma unroll
            for (int i = 0; i < 4; i++)
#pragma unroll
                for (int j = 0; j < 4; j++) acc[i][j] += ra[i] * rb[j];
        }
        __syncthreads();
    }
#pragma unroll
    for (int i = 0; i < 4; i++) {
        int row = bm + ty * 4 + i;
        int col = bn + tx * 4;
        float4 r;
        r.x = acc[i][0] + bias[col+0];
        r.y = acc[i][1] + bias[col+1];
        r.z = acc[i][2] + bias[col+2];
        r.w = acc[i][3] + bias[col+3];
        *reinterpret_cast<float4*>(&C[(size_t)row * Nout + col]) = r;
    }
}

__device__ void scan256(const int* __restrict__ in, int* __restrict__ out, int items, int* sums)
{
    int tid = threadIdx.x;
    int loc[16];
    int s = 0;
    for (int j = 0; j < items; j++) { loc[j] = in[tid * items + j]; s += loc[j]; }
    sums[tid] = s;
    __syncthreads();
    for (int off = 1; off < 256; off <<= 1) {
        int add = (tid >= off) ? sums[tid - off] : 0;
        __syncthreads();
        sums[tid] += add;
        __syncthreads();
    }
    int run = (tid == 0) ? 0 : sums[tid - 1];
    for (int j = 0; j < items; j++) { out[tid * items + j] = run; run += loc[j]; }
    if (tid == 255) out[256 * items] = sums[255];
}

// ================= THE single fused kernel =================
__global__ __launch_bounds__(NTHR, 2)
void fused_kernel(const float* __restrict__ node_in, const float* __restrict__ edge_in,
                  const int* __restrict__ src, const int* __restrict__ dst,
                  const int* __restrict__ lg_src, const int* __restrict__ lg_dst,
                  const float* __restrict__ nqW, const float* __restrict__ nqb,
                  const float* __restrict__ nkW, const float* __restrict__ nkb,
                  const float* __restrict__ nvW, const float* __restrict__ nvb,
                  const float* __restrict__ eqW, const float* __restrict__ eqb,
                  const float* __restrict__ ekW, const float* __restrict__ ekb,
                  const float* __restrict__ evW, const float* __restrict__ evb,
                  const float* __restrict__ ncW, const float* __restrict__ ncb,
                  const float* __restrict__ ecW, const float* __restrict__ ecb,
                  float* __restrict__ out)
{
    __shared__ float s_buf[4096];          // 16KB, reused per phase
    int bid = blockIdx.x, tid = threadIdx.x;
    int warp = tid >> 5, lane = tid & 31;
    int gw = bid * 8 + warp;
    const int nwarps = NBLK * 8;           // 2368
    int gtid = bid * NTHR + tid;
    const int gsz = NBLK * NTHR;           // 75776

    // ---------------- P0: V gemms + k-proj + counts + transposes ----------------
    for (int t = bid; t < 384; t += NBLK) {
        if (t < 128) gemm_tile(node_in, nvW, nvb, g_nv, (t >> 3) * 64, (t & 7) * 64, NH*FN, FN, s_buf);
        else { int t2 = t - 128; gemm_tile(edge_in, evW, evb, g_ev, (t2 >> 2) * 64, (t2 & 3) * 64, NH*FE, FE, s_buf); }
    }
    for (int w = gw; w < NN + EE; w += nwarps) {
        if (w < NN) {
            float4 xv = reinterpret_cast<const float4*>(node_in + w * FN)[lane];
            float4 w0 = reinterpret_cast<const float4*>(nkW + 0*FN)[lane];
            float4 w1 = reinterpret_cast<const float4*>(nkW + 1*FN)[lane];
            float4 w2 = reinterpret_cast<const float4*>(nkW + 2*FN)[lane];
            float4 w3 = reinterpret_cast<const float4*>(nkW + 3*FN)[lane];
            float p0 = xv.x*w0.x + xv.y*w0.y + xv.z*w0.z + xv.w*w0.w;
            float p1 = xv.x*w1.x + xv.y*w1.y + xv.z*w1.z + xv.w*w1.w;
            float p2 = xv.x*w2.x + xv.y*w2.y + xv.z*w2.z + xv.w*w2.w;
            float p3 = xv.x*w3.x + xv.y*w3.y + xv.z*w3.z + xv.w*w3.w;
            p0 = wredsum(p0); p1 = wredsum(p1); p2 = wredsum(p2); p3 = wredsum(p3);
            if (lane < 4) {
                float v = (lane == 0) ? p0 : (lane == 1) ? p1 : (lane == 2) ? p2 : p3;
                g_nk[w * 4 + lane] = v + nkb[lane];
            }
        } else {
            int row = w - NN;
            float2 xv = reinterpret_cast<const float2*>(edge_in + row * FE)[lane];
            float2 w0 = reinterpret_cast<const float2*>(ekW + 0*FE)[lane];
            float2 w1 = reinterpret_cast<const float2*>(ekW + 1*FE)[lane];
            float2 w2 = reinterpret_cast<const float2*>(ekW + 2*FE)[lane];
            float2 w3 = reinterpret_cast<const float2*>(ekW + 3*FE)[lane];
            float p0 = xv.x*w0.x + xv.y*w0.y;
            float p1 = xv.x*w1.x + xv.y*w1.y;
            float p2 = xv.x*w2.x + xv.y*w2.y;
            float p3 = xv.x*w3.x + xv.y*w3.y;
            p0 = wredsum(p0); p1 = wredsum(p1); p2 = wredsum(p2); p3 = wredsum(p3);
            if (lane < 4) {
                float v = (lane == 0) ? p0 : (lane == 1) ? p1 : (lane == 2) ? p2 : p3;
                g_ek[row * 4 + lane] = v + ekb[lane];
            }
        }
    }
    for (int i = gtid; i < EE + NLE; i += gsz) {
        if (i < EE) atomicAdd(&g_cnt_n[src[i]], 1);
        else        atomicAdd(&g_cnt_e[lg_src[i - EE]], 1);
    }
    for (int i = gtid; i < FN*FN + FE*FE + 512*FN + 256*FE; i += gsz) {
        if (i < FN*FN) {
            int o = i >> 7, f = i & 127;
            g_ncWT[f*FN + o] = ncW[i];
        } else if (i < FN*FN + FE*FE) {
            int k = i - FN*FN;
            int o = k >> 6, f = k & 63;
            g_ecWT[f*FE + o] = ecW[k];
        } else if (i < FN*FN + FE*FE + 512*FN) {
            int k = i - (FN*FN + FE*FE);
            int o = k >> 7, j = k & 127;
            g_nqWT[j*512 + o] = nqW[k];
        } else {
            int k = i - (FN*FN + FE*FE + 512*FN);
            int o = k >> 6, j = k & 63;
            g_eqWT[j*256 + o] = eqW[k];
        }
    }
    grid_sync();

    // ---------------- P1: scans + y/ks ----------------
    if (bid == 0)      scan256(g_cnt_n, g_off_n, 4,  (int*)s_buf);
    else if (bid == 1) scan256(g_cnt_e, g_off_e, 16, (int*)s_buf);
    else {
        for (int t = bid - 2; t < 160; t += NBLK - 2) {
            if (t < 32) {
                int h = t >> 3;
                int f = tid & 127, part = tid >> 7;
                int m0 = t * 32 + part * 16;
                float a0 = 0.f, a1 = 0.f, a2 = 0.f, a3 = 0.f;
                for (int m = m0; m < m0 + 16; m++) {
                    float x = node_in[m * FN + f];
                    const float* kp = g_nk + m * 4;
                    a0 += kp[0]*x; a1 += kp[1]*x; a2 += kp[2]*x; a3 += kp[3]*x;
                }
                atomicAdd(&g_yn[h*512 + 0*FN + f], a0);
                atomicAdd(&g_yn[h*512 + 1*FN + f], a1);
                atomicAdd(&g_yn[h*512 + 2*FN + f], a2);
                atomicAdd(&g_yn[h*512 + 3*FN + f], a3);
                if (f < 4) {
                    float s = 0.f;
                    for (int m = m0; m < m0 + 16; m++) s += g_nk[m * 4 + f];
                    atomicAdd(&g_ksn[h*4 + f], s);
                }
            } else {
                int tc = t - 32;
                int h = tc >> 5;
                int f = tid & 63, part = tid >> 6;
                int m0 = tc * 32 + part * 8;
                float a0 = 0.f, a1 = 0.f, a2 = 0.f, a3 = 0.f;
                for (int m = m0; m < m0 + 8; m++) {
                    float x = edge_in[m * FE + f];
                    const float* kp = g_ek + m * 4;
                    a0 += kp[0]*x; a1 += kp[1]*x; a2 += kp[2]*x; a3 += kp[3]*x;
                }
                atomicAdd(&g_ye[h*256 + 0*FE + f], a0);
                atomicAdd(&g_ye[h*256 + 1*FE + f], a1);
                atomicAdd(&g_ye[h*256 + 2*FE + f], a2);
                atomicAdd(&g_ye[h*256 + 3*FE + f], a3);
                if (f < 4) {
                    float s = 0.f;
                    for (int m = m0; m < m0 + 8; m++) s += g_ek[m * 4 + f];
                    atomicAdd(&g_kse[h*4 + f], s);
                }
            }
        }
    }
    grid_sync();

    // ---------------- P2: CSR fill + t ----------------
    for (int i = gtid; i < EE + NLE; i += gsz) {
        if (i < EE) {
            int s = src[i];
            int p = g_off_n[s] + atomicAdd(&g_fc_n[s], 1);
            g_lst_n[p] = i;
        } else {
            int l = i - EE;
            int s = lg_src[l];
            int p = g_off_e[s] + atomicAdd(&g_fc_e[s], 1);
            g_lst_e[p] = l;
        }
    }
    for (int w = gw; w < 768; w += nwarps) {
        if (w < 512) {
            int h = w >> 7, f = w & 127;
            float acc = 0.f;
#pragma unroll
            for (int b = 0; b < 4; b++) {
                float4 wv = *reinterpret_cast<const float4*>(&nqW[(size_t)(b*FN + f) * FN + lane*4]);
                float4 yv = *reinterpret_cast<const float4*>(&g_yn[h*512 + b*FN + lane*4]);
                acc += wv.x*yv.x + wv.y*yv.y + wv.z*yv.z + wv.w*yv.w;
            }
            acc = wredsum(acc);
            if (lane == 0) {
                float bt = 0.f;
#pragma unroll
                for (int b = 0; b < 4; b++) bt += nqb[b*FN + f] * g_ksn[h*4 + b];
                g_tn[h*FN + f] = acc + bt;
            }
        } else {
            int w2 = w - 512;
            int h = w2 >> 6, f = w2 & 63;
            float acc = 0.f;
#pragma unroll
            for (int b = 0; b < 4; b++) {
                float2 wv = *reinterpret_cast<const float2*>(&eqW[(size_t)(b*FE + f) * FE + lane*2]);
                float2 yv = *reinterpret_cast<const float2*>(&g_ye[h*256 + b*FE + lane*2]);
                acc += wv.x*yv.x + wv.y*yv.y;
            }
            acc = wredsum(acc);
            if (lane == 0) {
                float bt = 0.f;
#pragma unroll
                for (int b = 0; b < 4; b++) bt += eqb[b*FE + f] * g_kse[h*4 + b];
                g_te[h*FE + f] = acc + bt;
            }
        }
    }
    grid_sync();

    // ---------------- P3: u + c ----------------
    for (int w = gw; w < 3104; w += nwarps) {
        if (w < 2048) {
            int h = w >> 9, bq = (w >> 7) & 3, j = w & 127;
            float4 wv = *reinterpret_cast<const float4*>(&g_nqWT[j*512 + bq*FN + lane*4]);
            float4 tv = *reinterpret_cast<const float4*>(&g_tn[h*FN + lane*4]);
            float acc = wv.x*tv.x + wv.y*tv.y + wv.z*tv.z + wv.w*tv.w;
            acc = wredsum(acc);
            if (lane == 0) g_un[h*512 + bq*FN + j] = acc;
        } else if (w < 3072) {
            int w2 = w - 2048;
            int h = w2 >> 8, bq = (w2 >> 6) & 3, j = w2 & 63;
            float2 wv = *reinterpret_cast<const float2*>(&g_eqWT[j*256 + bq*FE + lane*2]);
            float2 tv = *reinterpret_cast<const float2*>(&g_te[h*FE + lane*2]);
            float acc = wv.x*tv.x + wv.y*tv.y;
            acc = wredsum(acc);
            if (lane == 0) g_ue[h*256 + bq*FE + j] = acc;
        } else if (w < 3088) {
            int w3 = w - 3072;
            int h = w3 >> 2, bq = w3 & 3;
            float4 bv = *reinterpret_cast<const float4*>(&nqb[bq*FN + lane*4]);
            float4 tv = *reinterpret_cast<const float4*>(&g_tn[h*FN + lane*4]);
            float acc = bv.x*tv.x + bv.y*tv.y + bv.z*tv.z + bv.w*tv.w;
            acc = wredsum(acc);
            if (lane == 0) g_cn[h*4 + bq] = acc;
        } else {
            int w3 = w - 3088;
            int h = w3 >> 2, bq = w3 & 3;
            float2 bv = *reinterpret_cast<const float2*>(&eqb[bq*FE + lane*2]);
            float2 tv = *reinterpret_cast<const float2*>(&g_te[h*FE + lane*2]);
            float acc = bv.x*tv.x + bv.y*tv.y;
            acc = wredsum(acc);
            if (lane == 0) g_ce[h*4 + bq] = acc;
        }
    }
    grid_sync();

    // ---------------- P4: raw scores ----------------
    for (int w = gw; w < NH*NN + NH*EE; w += nwarps) {
        if (w < NH*NN) {
            int h = w >> 10, m = w & (NN - 1);
            int a = m >> 2, b = m & 3;
            int row = h * 256 + a;
            float4 uv = *reinterpret_cast<const float4*>(&g_un[h*512 + b*FN + lane*4]);
            float4 xv = *reinterpret_cast<const float4*>(&node_in[row*FN + lane*4]);
            float d = xv.x*uv.x + xv.y*uv.y + xv.z*uv.z + xv.w*uv.w;
            d = wredsum(d);
            if (lane == 0) g_nsa[h*NN + m] = d + g_cn[h*4+b];
        } else {
            int w2 = w - NH*NN;
            int h = w2 >> 12, m = w2 & (EE - 1);
            int a = m >> 2, b = m & 3;
            int row = h * 1024 + a;
            float2 uv = *reinterpret_cast<const float2*>(&g_ue[h*256 + b*FE + lane*2]);
            float2 xv = *reinterpret_cast<const float2*>(&edge_in[row*FE + lane*2]);
            float d = xv.x*uv.x + xv.y*uv.y;
            d = wredsum(d);
            if (lane == 0) g_esa[h*EE + m] = d + g_ce[h*4+b];
        }
    }
    grid_sync();

    // ---------------- P5: softmax (8 blocks; separate output buffers) ----------------
    if (bid < 8) {
        const float* in; float* ob; int cnt;
        if (bid < 4) { in = g_nsa + bid*NN;     ob = g_nsa2 + bid*NN;     cnt = 4;  }
        else         { in = g_esa + (bid-4)*EE; ob = g_esa2 + (bid-4)*EE; cnt = 16; }
        float v[16];
        float m = -3e38f;
        for (int j = 0; j < cnt; j++) { v[j] = in[tid + j*NTHR]; m = fmaxf(m, v[j]); }
        float mx = blkmax(m, s_buf);
        float sum = 0.f;
        for (int j = 0; j < cnt; j++) { v[j] = expf(v[j] - mx); sum += v[j]; }
        float tot = blksum(sum, s_buf);
        float inv = 1.f / tot;
        for (int j = 0; j < cnt; j++) ob[tid + j*NTHR] = v[j] * inv;
    }
    grid_sync();

    // ---------------- P6: outputs + cleanup ----------------
    for (int t = bid; t < 1024; t += NBLK) {
        if (t < 512) {
            // node: 8 rows/task; col = tid&127, rg = tid>>7 handles 4 rows
            float (*agg)[FN] = reinterpret_cast<float(*)[FN]>(s_buf);
            int h = t >> 7;
            int i0 = (t & 127) * 8;
            int col = tid & 127, rg = tid >> 7;
#pragma unroll
            for (int k = 0; k < 4; k++) {
                int lr = rg * 4 + k;
                int i = i0 + lr;
                int s0 = g_off_n[i], s1 = g_off_n[i + 1];
                float acc = 0.f;
                for (int p = s0; p < s1; p++) {
                    int e = g_lst_n[p];
                    int d = dst[e];
                    bool win = true;
                    for (int p2 = s0; p2 < s1; p2++) {
                        int e2 = g_lst_n[p2];
                        if (e2 > e && dst[e2] == d) win = false;   // last write wins
                    }
                    if (win) acc += g_esa2[h*EE + e] * g_nv[h*(NN*FN) + d*FN + col];
                }
                agg[lr][col] = acc;
            }
            __syncthreads();
            float bb = ncb[col];
            float a0 = bb, a1 = bb, a2 = bb, a3 = bb;
#pragma unroll 4
            for (int f = 0; f < FN; f++) {
                float w = g_ncWT[f*FN + col];
                a0 += agg[rg*4+0][f] * w;
                a1 += agg[rg*4+1][f] * w;
                a2 += agg[rg*4+2][f] * w;
                a3 += agg[rg*4+3][f] * w;
            }
            float* o = out + h*(NN*FN) + (i0 + rg*4)*FN + col;
            o[0*FN] = fmaxf(a0, 0.f);
            o[1*FN] = fmaxf(a1, 0.f);
            o[2*FN] = fmaxf(a2, 0.f);
            o[3*FN] = fmaxf(a3, 0.f);
            __syncthreads();
        } else {
            // edge: 32 rows/task; col = tid&63, rg = tid>>6 handles 8 rows
            float (*agg)[FE] = reinterpret_cast<float(*)[FE]>(s_buf);
            int t2 = t - 512;
            int h = t2 >> 7;
            int i0 = (t2 & 127) * 32;
            int col = tid & 63, rg = tid >> 6;
#pragma unroll
            for (int k = 0; k < 8; k++) {
                int lr = rg * 8 + k;
                int i = i0 + lr;
                int s0 = g_off_e[i], s1 = g_off_e[i + 1];
                float acc = 0.f;
                for (int p = s0; p < s1; p++) {
                    int l = g_lst_e[p];
                    int ld = lg_dst[l];
                    bool win = true;
                    for (int p2 = s0; p2 < s1; p2++) {
                        int l2 = g_lst_e[p2];
                        if (l2 > l && lg_dst[l2] == ld) win = false;
                    }
                    if (win) acc += g_ev[h*(EE*FE) + ld*FE + col];
                }
                acc *= g_nsa2[h*NN + dst[i]];
                agg[lr][col] = acc;
            }
            __syncthreads();
            float a[8];
            float bb = ecb[col];
#pragma unroll
            for (int k = 0; k < 8; k++) a[k] = bb;
#pragma unroll 4
            for (int f = 0; f < FE; f++) {
                float w = g_ecWT[f*FE + col];
#pragma unroll
                for (int k = 0; k < 8; k++) a[k] += agg[rg*8 + k][f] * w;
            }
#pragma unroll
            for (int k = 0; k < 8; k++) {
                int i = i0 + rg*8 + k;
                out[NODE_OUT_SZ + h*(EE*FE) + i*FE + col] = fmaxf(a[k], 0.f);
            }
            __syncthreads();
        }
    }
    // cleanup for next run
    for (int i = gtid; i < NN; i += gsz) { g_cnt_n[i] = 0; g_fc_n[i] = 0; }
    for (int i = gtid; i < EE; i += gsz) { g_cnt_e[i] = 0; g_fc_e[i] = 0; }
    for (int i = gtid; i < NH*512; i += gsz) g_yn[i] = 0.f;
    for (int i = gtid; i < NH*256; i += gsz) g_ye[i] = 0.f;
    if (gtid < 16) { g_ksn[gtid] = 0.f; g_kse[gtid] = 0.f; }
}

// ---------------- launcher: ONE launch ----------------
extern "C" void kernel_launch(void* const* d_in, const int* in_sizes, int n_in,
                              void* d_out, int out_size)
{
    const float* node_inputs = (const float*)d_in[0];
    const float* edge_inputs = (const float*)d_in[1];
    const int*   src         = (const int*)d_in[2];
    const int*   dst         = (const int*)d_in[3];
    const int*   lg_src      = (const int*)d_in[4];
    const int*   lg_dst      = (const int*)d_in[5];
    const float* nqW = (const float*)d_in[6];
    const float* nqb = (const float*)d_in[7];
    const float* nkW = (const float*)d_in[8];
    const float* nkb = (const float*)d_in[9];
    const float* nvW = (const float*)d_in[10];
    const float* nvb = (const float*)d_in[11];
    const float* eqW = (const float*)d_in[12];
    const float* eqb = (const float*)d_in[13];
    const float* ekW = (const float*)d_in[14];
    const float* ekb = (const float*)d_in[15];
    const float* evW = (const float*)d_in[16];
    const float* evb = (const float*)d_in[17];
    const float* ncW = (const float*)d_in[18];
    const float* ncb = (const float*)d_in[19];
    const float* ecW = (const float*)d_in[20];
    const float* ecb = (const float*)d_in[21];
    float* out = (float*)d_out;

    fused_kernel<<<NBLK, NTHR>>>(node_inputs, edge_inputs, src, dst, lg_src, lg_dst,
                                 nqW, nqb, nkW, nkb, nvW, nvb,
                                 eqW, eqb, ekW, ekb, evW, evb,
                                 ncW, ncb, ecW, ecb, out);
}

// round 12
// speedup vs baseline: 1.4997x; 1.4997x over previous
#include <cuda_runtime.h>
#include <math.h>

#define NH 4
#define NN 1024
#define EE 4096
#define NLE 16384
#define FN 128
#define FE 64
#define NODE_OUT_SZ (NH*NN*FN)   /* 524288 */

// ---------------- scratch (device globals; zero-initialized at load) ----------------
__device__ float g_nv[NN*NH*FN];
__device__ float g_ev[EE*NH*FE];
__device__ float g_nk[NN*NH];          // flat k-linear output [row][c]
__device__ float g_ek[EE*NH];
__device__ float g_yn[NH*512];         // y[h][b*128+f]  (atomics; zeroed each run)
__device__ float g_ye[NH*256];
__device__ float g_ksn[16];            // ks[h][b]       (atomics; zeroed each run)
__device__ float g_kse[16];
__device__ float g_tn[NH*FN];          // t[h][f]
__device__ float g_te[NH*FE];
__device__ float g_un[NH*512];         // u[h][b*128+j]
__device__ float g_ue[NH*256];
__device__ float g_cn[16];             // c[h][b]
__device__ float g_ce[16];
__device__ float g_nsa[NH*NN];
__device__ float g_esa[NH*EE];
__device__ int   g_cnt_n[NN], g_fc_n[NN], g_off_n[NN+1], g_lst_n[EE];
__device__ int   g_cnt_e[EE], g_fc_e[EE], g_off_e[EE+1], g_lst_e[NLE];
__device__ float g_ncWT[FN*FN];
__device__ float g_ecWT[FE*FE];
__device__ float g_nqWT[FN*512];       // nqWT[j*512+o] = nqW[o*128+j]
__device__ float g_eqWT[FE*256];       // eqWT[j*256+o] = eqW[o*64+j]

__device__ __forceinline__ float wredsum(float v)
{
#pragma unroll
    for (int o = 16; o; o >>= 1) v += __shfl_xor_sync(0xffffffffu, v, o);
    return v;
}

// ---------------- gemm tile: C[64,64] of A[M,K] @ W[N,K]^T + bias ----------------
__device__ __forceinline__
void gemm_tile(const float* __restrict__ A, const float* __restrict__ W,
               const float* __restrict__ bias, float* __restrict__ C,
               int bm, int bn, int Nout, int K)
{
    __shared__ float As[32][64];
    __shared__ float Bs[32][64];
    int tid = threadIdx.x;
    int tx = tid & 15, ty = tid >> 4;

    float acc[4][4];
#pragma unroll
    for (int i = 0; i < 4; i++)
#pragma unroll
        for (int j = 0; j < 4; j++) acc[i][j] = 0.f;

    for (int k0 = 0; k0 < K; k0 += 32) {
#pragma unroll
        for (int j = 0; j < 2; j++) {
            int f4 = tid + j * 256;
            int m  = f4 >> 3;
            int k4 = f4 & 7;
            float4 va = *reinterpret_cast<const float4*>(&A[(size_t)(bm + m) * K + k0 + k4 * 4]);
            As[k4*4+0][m] = va.x; As[k4*4+1][m] = va.y; As[k4*4+2][m] = va.z; As[k4*4+3][m] = va.w;
            float4 vb = *reinterpret_cast<const float4*>(&W[(size_t)(bn + m) * K + k0 + k4 * 4]);
            Bs[k4*4+0][m] = vb.x; Bs[k4*4+1][m] = vb.y; Bs[k4*4+2][m] = vb.z; Bs[k4*4+3][m] = vb.w;
        }
        __syncthreads();
#pragma unroll
        for (int kk = 0; kk < 32; kk++) {
            float4 a = *reinterpret_cast<const float4*>(&As[kk][ty * 4]);
            float4 b = *reinterpret_cast<const float4*>(&Bs[kk][tx * 4]);
            float ra[4] = {a.x, a.y, a.z, a.w};
            float rb[4] = {b.x, b.y, b.z, b.w};
#pragma unroll
            for (int i = 0; i < 4; i++)
#pragma unroll
                for (int j = 0; j < 4; j++) acc[i][j] += ra[i] * rb[j];
        }
        __syncthreads();
    }
#pragma unroll
    for (int i = 0; i < 4; i++) {
        int row = bm + ty * 4 + i;
        int col = bn + tx * 4;
        float4 r;
        r.x = acc[i][0] + bias[col+0];
        r.y = acc[i][1] + bias[col+1];
        r.z = acc[i][2] + bias[col+2];
        r.w = acc[i][3] + bias[col+3];
        *reinterpret_cast<float4*>(&C[(size_t)row * Nout + col]) = r;
    }
}

// ---------------- K1: prep — kproj + counts + transposes + V gemms ----------------
// grid 1504 x 256: [0,640) kproj warps, [640,720) counts, [720,1120) transposes, [1120,1504) V gemms
__global__ __launch_bounds__(256)
void prep_kernel(const float* __restrict__ node_in, const float* __restrict__ edge_in,
                 const float* __restrict__ nkW, const float* __restrict__ nkb,
                 const float* __restrict__ ekW, const float* __restrict__ ekb,
                 const int* __restrict__ src, const int* __restrict__ lg_src,
                 const float* __restrict__ ncW, const float* __restrict__ ecW,
                 const float* __restrict__ nqW, const float* __restrict__ eqW,
                 const float* __restrict__ nvW, const float* __restrict__ nvb,
                 const float* __restrict__ evW, const float* __restrict__ evb)
{
    int bid = blockIdx.x, tid = threadIdx.x;
    if (bid < 640) {
        int w = bid * 8 + (tid >> 5), lane = tid & 31;
        if (w < NN) {
            float4 xv = reinterpret_cast<const float4*>(node_in + w * FN)[lane];
            float4 w0 = reinterpret_cast<const float4*>(nkW + 0*FN)[lane];
            float4 w1 = reinterpret_cast<const float4*>(nkW + 1*FN)[lane];
            float4 w2 = reinterpret_cast<const float4*>(nkW + 2*FN)[lane];
            float4 w3 = reinterpret_cast<const float4*>(nkW + 3*FN)[lane];
            float p0 = xv.x*w0.x + xv.y*w0.y + xv.z*w0.z + xv.w*w0.w;
            float p1 = xv.x*w1.x + xv.y*w1.y + xv.z*w1.z + xv.w*w1.w;
            float p2 = xv.x*w2.x + xv.y*w2.y + xv.z*w2.z + xv.w*w2.w;
            float p3 = xv.x*w3.x + xv.y*w3.y + xv.z*w3.z + xv.w*w3.w;
            p0 = wredsum(p0); p1 = wredsum(p1); p2 = wredsum(p2); p3 = wredsum(p3);
            if (lane < 4) {
                float v = (lane == 0) ? p0 : (lane == 1) ? p1 : (lane == 2) ? p2 : p3;
                g_nk[w * 4 + lane] = v + nkb[lane];
            }
        } else {
            int row = w - NN;
            float2 xv = reinterpret_cast<const float2*>(edge_in + row * FE)[lane];
            float2 w0 = reinterpret_cast<const float2*>(ekW + 0*FE)[lane];
            float2 w1 = reinterpret_cast<const float2*>(ekW + 1*FE)[lane];
            float2 w2 = reinterpret_cast<const float2*>(ekW + 2*FE)[lane];
            float2 w3 = reinterpret_cast<const float2*>(ekW + 3*FE)[lane];
            float p0 = xv.x*w0.x + xv.y*w0.y;
            float p1 = xv.x*w1.x + xv.y*w1.y;
            float p2 = xv.x*w2.x + xv.y*w2.y;
            float p3 = xv.x*w3.x + xv.y*w3.y;
            p0 = wredsum(p0); p1 = wredsum(p1); p2 = wredsum(p2); p3 = wredsum(p3);
            if (lane < 4) {
                float v = (lane == 0) ? p0 : (lane == 1) ? p1 : (lane == 2) ? p2 : p3;
                g_ek[row * 4 + lane] = v + ekb[lane];
            }
        }
    } else if (bid < 720) {
        int idx = (bid - 640) * 256 + tid;
        if (idx < EE)            atomicAdd(&g_cnt_n[src[idx]], 1);
        else if (idx < EE + NLE) atomicAdd(&g_cnt_e[lg_src[idx - EE]], 1);
    } else if (bid < 1120) {
        int idx = (bid - 720) * 256 + tid;     // 0..102399
        if (idx < FN*FN) {
            int o = idx >> 7, f = idx & 127;
            g_ncWT[f*FN + o] = ncW[idx];
        } else if (idx < FN*FN + FE*FE) {
            int i = idx - FN*FN;
            int o = i >> 6, f = i & 63;
            g_ecWT[f*FE + o] = ecW[i];
        } else if (idx < FN*FN + FE*FE + 512*FN) {
            int i = idx - (FN*FN + FE*FE);
            int o = i >> 7, j = i & 127;
            g_nqWT[j*512 + o] = nqW[i];
        } else {
            int i = idx - (FN*FN + FE*FE + 512*FN);
            int o = i >> 6, j = i & 63;
            g_eqWT[j*256 + o] = eqW[i];
        }
    } else {
        int b = bid - 1120;
        if (b < 128) {
            gemm_tile(node_in, nvW, nvb, g_nv, (b >> 3) * 64, (b & 7) * 64, NH*FN, FN);
        } else {
            b -= 128;
            gemm_tile(edge_in, evW, evb, g_ev, (b >> 2) * 64, (b & 3) * 64, NH*FE, FE);
        }
    }
}

// ---------------- K2: scans + wide y/ks reduction ----------------
__device__ void scan256(const int* __restrict__ in, int* __restrict__ out, int items)
{
    __shared__ int sums[256];
    int tid = threadIdx.x;
    int loc[16];
    int s = 0;
    for (int j = 0; j < items; j++) { loc[j] = in[tid * items + j]; s += loc[j]; }
    sums[tid] = s;
    __syncthreads();
    for (int off = 1; off < 256; off <<= 1) {
        int add = (tid >= off) ? sums[tid - off] : 0;
        __syncthreads();
        sums[tid] += add;
        __syncthreads();
    }
    int run = (tid == 0) ? 0 : sums[tid - 1];
    for (int j = 0; j < items; j++) { out[tid * items + j] = run; run += loc[j]; }
    if (tid == 255) out[256 * items] = sums[255];
}

// grid 322 x 256: 0 node-scan, 1 edge-scan, [2,66) node-y (16 rows/blk), [66,322) edge-y (16 rows/blk)
__global__ __launch_bounds__(256)
void scan_y_kernel(const float* __restrict__ node_in, const float* __restrict__ edge_in)
{
    int bid = blockIdx.x, tid = threadIdx.x;
    if (bid == 0)      { scan256(g_cnt_n, g_off_n, 4);  return; }
    else if (bid == 1) { scan256(g_cnt_e, g_off_e, 16); return; }
    else if (bid < 66) {
        int blk = bid - 2;                 // 0..63, head h = blk/16
        int h = blk >> 4;
        int f = tid & 127, part = tid >> 7;
        int m0 = blk * 16 + part * 8;
        float a0 = 0.f, a1 = 0.f, a2 = 0.f, a3 = 0.f;
        for (int m = m0; m < m0 + 8; m++) {
            float x = node_in[m * FN + f];
            const float* kp = g_nk + m * 4;
            a0 += kp[0]*x; a1 += kp[1]*x; a2 += kp[2]*x; a3 += kp[3]*x;
        }
        atomicAdd(&g_yn[h*512 + 0*FN + f], a0);
        atomicAdd(&g_yn[h*512 + 1*FN + f], a1);
        atomicAdd(&g_yn[h*512 + 2*FN + f], a2);
        atomicAdd(&g_yn[h*512 + 3*FN + f], a3);
        if (f < 4 && part == 0) {
            float s = 0.f;
            for (int m = blk * 16; m < blk * 16 + 16; m++) s += g_nk[m * 4 + f];
            atomicAdd(&g_ksn[h*4 + f], s);
        }
    } else {
        int blk = bid - 66;                // 0..255, head h = blk/64
        int h = blk >> 6;
        int f = tid & 63, part = tid >> 6;
        int m0 = blk * 16 + part * 4;
        float a0 = 0.f, a1 = 0.f, a2 = 0.f, a3 = 0.f;
        for (int m = m0; m < m0 + 4; m++) {
            float x = edge_in[m * FE + f];
            const float* kp = g_ek + m * 4;
            a0 += kp[0]*x; a1 += kp[1]*x; a2 += kp[2]*x; a3 += kp[3]*x;
        }
        atomicAdd(&g_ye[h*256 + 0*FE + f], a0);
        atomicAdd(&g_ye[h*256 + 1*FE + f], a1);
        atomicAdd(&g_ye[h*256 + 2*FE + f], a2);
        atomicAdd(&g_ye[h*256 + 3*FE + f], a3);
        if (f < 4 && part == 0) {
            float s = 0.f;
            for (int m = blk * 16; m < blk * 16 + 16; m++) s += g_ek[m * 4 + f];
            atomicAdd(&g_kse[h*4 + f], s);
        }
    }
}

// ---------------- K3: CSR fill + t (warp per (h,f)) ----------------
// grid 176 x 256: [0,80) fill, [80,176) t warps (768)
__global__ __launch_bounds__(256)
void fill_t_kernel(const int* __restrict__ src, const int* __restrict__ lg_src,
                   const float* __restrict__ nqW, const float* __restrict__ nqb,
                   const float* __restrict__ eqW, const float* __restrict__ eqb)
{
    int bid = blockIdx.x, tid = threadIdx.x;
    if (bid < 80) {
        int idx = bid * 256 + tid;
        if (idx < EE) {
            int s = src[idx];
            int p = g_off_n[s] + atomicAdd(&g_fc_n[s], 1);
            g_lst_n[p] = idx;
        } else if (idx < EE + NLE) {
            int l = idx - EE;
            int s = lg_src[l];
            int p = g_off_e[s] + atomicAdd(&g_fc_e[s], 1);
            g_lst_e[p] = l;
        }
        return;
    }
    int w = (bid - 80) * 8 + (tid >> 5), lane = tid & 31;
    if (w < 512) {
        int h = w >> 7, f = w & 127;
        float acc = 0.f;
#pragma unroll
        for (int b = 0; b < 4; b++) {
            float4 wv = *reinterpret_cast<const float4*>(&nqW[(size_t)(b*FN + f) * FN + lane*4]);
            float4 yv = *reinterpret_cast<const float4*>(&g_yn[h*512 + b*FN + lane*4]);
            acc += wv.x*yv.x + wv.y*yv.y + wv.z*yv.z + wv.w*yv.w;
        }
        acc = wredsum(acc);
        if (lane == 0) {
            float bt = 0.f;
#pragma unroll
            for (int b = 0; b < 4; b++) bt += nqb[b*FN + f] * g_ksn[h*4 + b];
            g_tn[h*FN + f] = acc + bt;
        }
    } else if (w < 768) {
        int w2 = w - 512;
        int h = w2 >> 6, f = w2 & 63;
        float acc = 0.f;
#pragma unroll
        for (int b = 0; b < 4; b++) {
            float2 wv = *reinterpret_cast<const float2*>(&eqW[(size_t)(b*FE + f) * FE + lane*2]);
            float2 yv = *reinterpret_cast<const float2*>(&g_ye[h*256 + b*FE + lane*2]);
            acc += wv.x*yv.x + wv.y*yv.y;
        }
        acc = wredsum(acc);
        if (lane == 0) {
            float bt = 0.f;
#pragma unroll
            for (int b = 0; b < 4; b++) bt += eqb[b*FE + f] * g_kse[h*4 + b];
            g_te[h*FE + f] = acc + bt;
        }
    }
}

// ---------------- K4: u + c (warp per output) ----------------
// grid 388 x 256
__global__ __launch_bounds__(256)
void uc_kernel(const float* __restrict__ nqb, const float* __restrict__ eqb)
{
    int w = blockIdx.x * 8 + (threadIdx.x >> 5), lane = threadIdx.x & 31;
    if (w < 2048) {
        int h = w >> 9, bq = (w >> 7) & 3, j = w & 127;
        float4 wv = *reinterpret_cast<const float4*>(&g_nqWT[j*512 + bq*FN + lane*4]);
        float4 tv = *reinterpret_cast<const float4*>(&g_tn[h*FN + lane*4]);
        float acc = wv.x*tv.x + wv.y*tv.y + wv.z*tv.z + wv.w*tv.w;
        acc = wredsum(acc);
        if (lane == 0) g_un[h*512 + bq*FN + j] = acc;
    } else if (w < 3072) {
        int w2 = w - 2048;
        int h = w2 >> 8, bq = (w2 >> 6) & 3, j = w2 & 63;
        float2 wv = *reinterpret_cast<const float2*>(&g_eqWT[j*256 + bq*FE + lane*2]);
        float2 tv = *reinterpret_cast<const float2*>(&g_te[h*FE + lane*2]);
        float acc = wv.x*tv.x + wv.y*tv.y;
        acc = wredsum(acc);
        if (lane == 0) g_ue[h*256 + bq*FE + j] = acc;
    } else if (w < 3088) {
        int w3 = w - 3072;
        int h = w3 >> 2, bq = w3 & 3;
        float4 bv = *reinterpret_cast<const float4*>(&nqb[bq*FN + lane*4]);
        float4 tv = *reinterpret_cast<const float4*>(&g_tn[h*FN + lane*4]);
        float acc = bv.x*tv.x + bv.y*tv.y + bv.z*tv.z + bv.w*tv.w;
        acc = wredsum(acc);
        if (lane == 0) g_cn[h*4 + bq] = acc;
    } else if (w < 3104) {
        int w3 = w - 3088;
        int h = w3 >> 2, bq = w3 & 3;
        float2 bv = *reinterpret_cast<const float2*>(&eqb[bq*FE + lane*2]);
        float2 tv = *reinterpret_cast<const float2*>(&g_te[h*FE + lane*2]);
        float acc = bv.x*tv.x + bv.y*tv.y;
        acc = wredsum(acc);
        if (lane == 0) g_ce[h*4 + bq] = acc;
    }
}

// ---------------- K5: raw scores ----------------
__global__ __launch_bounds__(256)
void scores_kernel(const float* __restrict__ node_in, const float* __restrict__ edge_in)
{
    int w = blockIdx.x * 8 + (threadIdx.x >> 5);
    int lane = threadIdx.x & 31;
    if (w < NH*NN) {
        int h = w >> 10, m = w & (NN - 1);
        int a = m >> 2, b = m & 3;
        int row = h * 256 + a;
        float4 uv = *reinterpret_cast<const float4*>(&g_un[h*512 + b*FN + lane*4]);
        float4 xv = *reinterpret_cast<const float4*>(&node_in[row*FN + lane*4]);
        float d = xv.x*uv.x + xv.y*uv.y + xv.z*uv.z + xv.w*uv.w;
        d = wredsum(d);
        if (lane == 0) g_nsa[h*NN + m] = d + g_cn[h*4+b];
    } else {
        int w2 = w - NH*NN;
        int h = w2 >> 12, m = w2 & (EE - 1);
        int a = m >> 2, b = m & 3;
        int row = h * 1024 + a;
        float2 uv = *reinterpret_cast<const float2*>(&g_ue[h*256 + b*FE + lane*2]);
        float2 xv = *reinterpret_cast<const float2*>(&edge_in[row*FE + lane*2]);
        float d = xv.x*uv.x + xv.y*uv.y;
        d = wredsum(d);
        if (lane == 0) g_esa[h*EE + m] = d + g_ce[h*4+b];
    }
}

// ---------------- K6: per-head softmax normalize (in place) ----------------
__global__ __launch_bounds__(1024)
void softmax_kernel()
{
    __shared__ float red[32];
    __shared__ float bc_max, bc_sum;
    int bid = blockIdx.x, tid = threadIdx.x;
    int warp = tid >> 5, lane = tid & 31;
    float* buf; int cnt;
    if (bid < 4) { buf = g_nsa + bid * NN;       cnt = 1; }
    else         { buf = g_esa + (bid - 4) * EE; cnt = 4; }

    float v[4];
    float m = -3e38f;
    for (int j = 0; j < cnt; j++) { v[j] = buf[tid + j*1024]; m = fmaxf(m, v[j]); }
#pragma unroll
    for (int o = 16; o; o >>= 1) m = fmaxf(m, __shfl_xor_sync(0xffffffffu, m, o));
    if (lane == 0) red[warp] = m;
    __syncthreads();
    if (tid == 0) {
        float x = red[0];
        for (int w = 1; w < 32; w++) x = fmaxf(x, red[w]);
        bc_max = x;
    }
    __syncthreads();
    float mx = bc_max;

    float sum = 0.f;
    for (int j = 0; j < cnt; j++) { v[j] = expf(v[j] - mx); sum += v[j]; }
#pragma unroll
    for (int o = 16; o; o >>= 1) sum += __shfl_xor_sync(0xffffffffu, sum, o);
    __syncthreads();
    if (lane == 0) red[warp] = sum;
    __syncthreads();
    if (tid == 0) {
        float x = 0.f;
        for (int w = 0; w < 32; w++) x += red[w];
        bc_sum = x;
    }
    __syncthreads();
    float inv = 1.f / bc_sum;
    for (int j = 0; j < cnt; j++) buf[tid + j*1024] = v[j] * inv;
}

// ---------------- K7: outputs (weight-reuse tiles) + cleanup ----------------
// grid 1040 x 256: [0,512) node (8 rows/blk), [512,1024) edge (32 rows/blk), [1024,1040) cleanup
__global__ __launch_bounds__(256)
void out_kernel(const int* __restrict__ dst, const int* __restrict__ lg_dst,
                const float* __restrict__ ncb, const float* __restrict__ ecb,
                float* __restrict__ out)
{
    int bid = blockIdx.x, tid = threadIdx.x;
    if (bid < 512) {
        // node: 8 rows; col = tid&127, rg = tid>>7 (0..1) handles 4 rows each
        __shared__ float agg[8][FN];
        int h = bid >> 7;
        int i0 = (bid & 127) * 8;
        int col = tid & 127, rg = tid >> 7;
#pragma unroll
        for (int k = 0; k < 4; k++) {
            int lr = rg * 4 + k;
            int i = i0 + lr;
            int s0 = g_off_n[i], s1 = g_off_n[i + 1];
            float acc = 0.f;
            for (int p = s0; p < s1; p++) {
                int e = g_lst_n[p];
                int d = dst[e];
                bool win = true;
                for (int p2 = s0; p2 < s1; p2++) {
                    int e2 = g_lst_n[p2];
                    if (e2 > e && dst[e2] == d) win = false;   // last write wins
                }
                if (win) acc += g_esa[h*EE + e] * g_nv[h*(NN*FN) + d*FN + col];
            }
            agg[lr][col] = acc;
        }
        __syncthreads();
        float bb = ncb[col];
        float a0 = bb, a1 = bb, a2 = bb, a3 = bb;
#pragma unroll 4
        for (int f = 0; f < FN; f++) {
            float w = g_ncWT[f*FN + col];
            a0 += agg[rg*4+0][f] * w;
            a1 += agg[rg*4+1][f] * w;
            a2 += agg[rg*4+2][f] * w;
            a3 += agg[rg*4+3][f] * w;
        }
        float* o = out + h*(NN*FN) + (i0 + rg*4)*FN + col;
        o[0*FN] = fmaxf(a0, 0.f);
        o[1*FN] = fmaxf(a1, 0.f);
        o[2*FN] = fmaxf(a2, 0.f);
        o[3*FN] = fmaxf(a3, 0.f);
    } else if (bid < 1024) {
        // edge: 32 rows; col = tid&63, rg = tid>>6 (0..3) handles 8 rows each
        __shared__ float agg[32][FE];
        int b = bid - 512;
        int h = b >> 7;
        int i0 = (b & 127) * 32;
        int col = tid & 63, rg = tid >> 6;
#pragma unroll
        for (int k = 0; k < 8; k++) {
            int lr = rg * 8 + k;
            int i = i0 + lr;
            int s0 = g_off_e[i], s1 = g_off_e[i + 1];
            float acc = 0.f;
            for (int p = s0; p < s1; p++) {
                int l = g_lst_e[p];
                int ld = lg_dst[l];
                bool win = true;
                for (int p2 = s0; p2 < s1; p2++) {
                    int l2 = g_lst_e[p2];
                    if (l2 > l && lg_dst[l2] == ld) win = false;
                }
                if (win) acc += g_ev[h*(EE*FE) + ld*FE + col];
            }
            acc *= g_nsa[h*NN + dst[i]];
            agg[lr][col] = acc;
        }
        __syncthreads();
        float a[8];
        float bb = ecb[col];
#pragma unroll
        for (int k = 0; k < 8; k++) a[k] = bb;
#pragma unroll 4
        for (int f = 0; f < FE; f++) {
            float w = g_ecWT[f*FE + col];
#pragma unroll
            for (int k = 0; k < 8; k++) a[k] += agg[rg*8 + k][f] * w;
        }
#pragma unroll
        for (int k = 0; k < 8; k++) {
            int i = i0 + rg*8 + k;
            out[NODE_OUT_SZ + h*(EE*FE) + i*FE + col] = fmaxf(a[k], 0.f);
        }
    } else {
        // cleanup for next run
        int idx = (bid - 1024) * 256 + tid;       // 0..4095
        for (int i = idx; i < NN; i += 4096) { g_cnt_n[i] = 0; g_fc_n[i] = 0; }
        for (int i = idx; i < EE; i += 4096) { g_cnt_e[i] = 0; g_fc_e[i] = 0; }
        if (idx < NH*512) g_yn[idx] = 0.f;
        if (idx < NH*256) g_ye[idx] = 0.f;
        if (idx < 16) { g_ksn[idx] = 0.f; g_kse[idx] = 0.f; }
    }
}

// ---------------- launcher ----------------
extern "C" void kernel_launch(void* const* d_in, const int* in_sizes, int n_in,
                              void* d_out, int out_size)
{
    const float* node_inputs = (const float*)d_in[0];
    const float* edge_inputs = (const float*)d_in[1];
    const int*   src         = (const int*)d_in[2];
    const int*   dst         = (const int*)d_in[3];
    const int*   lg_src      = (const int*)d_in[4];
    const int*   lg_dst      = (const int*)d_in[5];
    const float* nqW = (const float*)d_in[6];
    const float* nqb = (const float*)d_in[7];
    const float* nkW = (const float*)d_in[8];
    const float* nkb = (const float*)d_in[9];
    const float* nvW = (const float*)d_in[10];
    const float* nvb = (const float*)d_in[11];
    const float* eqW = (const float*)d_in[12];
    const float* eqb = (const float*)d_in[13];
    const float* ekW = (const float*)d_in[14];
    const float* ekb = (const float*)d_in[15];
    const float* evW = (const float*)d_in[16];
    const float* evb = (const float*)d_in[17];
    const float* ncW = (const float*)d_in[18];
    const float* ncb = (const float*)d_in[19];
    const float* ecW = (const float*)d_in[20];
    const float* ecb = (const float*)d_in[21];
    float* out = (float*)d_out;

    prep_kernel<<<1504, 256>>>(node_inputs, edge_inputs, nkW, nkb, ekW, ekb,
                               src, lg_src, ncW, ecW, nqW, eqW,
                               nvW, nvb, evW, evb);
    scan_y_kernel<<<322, 256>>>(node_inputs, edge_inputs);
    fill_t_kernel<<<176, 256>>>(src, lg_src, nqW, nqb, eqW, eqb);
    uc_kernel<<<388, 256>>>(nqb, eqb);
    scores_kernel<<<2560, 256>>>(node_inputs, edge_inputs);
    softmax_kernel<<<8, 1024>>>();
    out_kernel<<<1040, 256>>>(dst, lg_dst, ncb, ecb, out);
}